// round 7
// baseline (speedup 1.0000x reference)
#include <cuda_runtime.h>
#include <math.h>
#include <stdint.h>

// Problem constants
#define NB 32
#define ND 64
#define NT 4096
#define NK 512
#define NTOK (NB * NT)          // 131072 tokens
#define TM 256                  // tokens per CTA tile
#define NTILE (NTOK / TM)       // 512 CTAs
#define ESTR 68                 // smem row stride (floats): (4*row+k)%32 distinct

// Output layout (float32, reference tuple flattened in order)
#define Q_OFF     ((size_t)1)
#define PERP_OFF  ((size_t)1 + (size_t)NB * ND * NT)
#define IDX_OFF   (PERP_OFF + 1)

// Margin threshold: |dist_approx - dist_frozen| <= ~8e-4; theta = 5x cushion
#define THETA 4e-3f
#define FLAG_CAP 32768

__device__ float g_loss;
__device__ unsigned int g_counts[NK];
__device__ unsigned int g_flagn;
__device__ int g_flags[FLAG_CAP];

// tf32 hi part via bit-mask (keep top 19 bits); lo = v - hi.
__device__ __forceinline__ float tf32hi(float v) {
    return __uint_as_float(__float_as_uint(v) & 0xFFFFE000u);
}

// m16n8k8 tf32 mma: D += A(16x8,row) * B(8x8,col)
__device__ __forceinline__ void mma_tf32(float* d, const uint32_t* a, const uint32_t* b) {
    asm volatile(
        "mma.sync.aligned.m16n8k8.row.col.f32.tf32.tf32.f32 "
        "{%0,%1,%2,%3}, {%4,%5,%6,%7}, {%8,%9}, {%0,%1,%2,%3};"
        : "+f"(d[0]), "+f"(d[1]), "+f"(d[2]), "+f"(d[3])
        : "r"(a[0]), "r"(a[1]), "r"(a[2]), "r"(a[3]), "r"(b[0]), "r"(b[1]));
}

// ================= K0: init =================
__global__ void vq_init() {
    int i = threadIdx.x;
    if (i == 0) { g_loss = 0.f; g_flagn = 0u; }
    if (i < NK) g_counts[i] = 0u;
}

// ================= K1: tf32x3 mma GEMM + argmin + margin flag =================
__global__ __launch_bounds__(512, 1) void vq_gemm(
    const float* __restrict__ in, const float* __restrict__ emb,
    float* __restrict__ out)
{
    extern __shared__ float smem[];
    float* sA = smem;                       // TM x ESTR        = 17408 f
    float* sB = sA + TM * ESTR;             // NK x ESTR        = 34816 f
    float* sEn = sB + NK * ESTR;            // NK
    float* sXn = sEn + NK;                  // TM

    const int tid = threadIdx.x;
    const int wid = tid >> 5;
    const int lane = tid & 31;
    const int grp = lane >> 2;              // 0..7  (fragment row group)
    const int qid = lane & 3;               // 0..3  (fragment k/col slot)

    const int token0 = blockIdx.x * TM;
    const int b = token0 >> 12;             // whole tile within one batch (4096%256==0)
    const int t0 = token0 & (NT - 1);

    // ---- Stage B (raw f32 codebook) : all threads, float4 ----
    {
        const float4* e4 = (const float4*)emb;
        for (int i = tid; i < NK * ND / 4; i += 512) {
            int code = i >> 4;              // 16 float4 per code
            int d4 = i & 15;
            float4 v = e4[i];
            *(float4*)(sB + code * ESTR + 4 * d4) = v;
        }
    }
    // ---- Stage A + frozen xn : threads 0..255 (one token each) ----
    if (tid < TM) {
        const float* xp = in + (size_t)b * ND * NT + (t0 + tid);
        float xn = 0.f;
        float* ar = sA + tid * ESTR;
        #pragma unroll
        for (int d = 0; d < ND; d++) {
            float x = xp[(size_t)d * NT];                 // coalesced
            xn = __fadd_rn(xn, __fmul_rn(x, x));          // FROZEN: no-fma sequential
            ar[d] = x;
        }
        sXn[tid] = xn;
    } else {
        // ---- frozen en (warp tree) : warps 8..15 ----
        for (int k = wid - 8; k < NK; k += 8) {
            const float* e = emb + k * ND;
            float a = __fmul_rn(e[lane], e[lane]);
            float c = __fmul_rn(e[lane + 32], e[lane + 32]);
            float acc = __fadd_rn(a, c);
            #pragma unroll
            for (int off = 16; off; off >>= 1)
                acc = __fadd_rn(acc, __shfl_down_sync(0xffffffffu, acc, off));
            if (lane == 0) sEn[k] = acc;
        }
    }
    __syncthreads();

    // ---- A fragments (hi/lo split) in registers: warp owns m-block wid*16 ----
    const int m0 = wid * 16;
    uint32_t ah[8][4], al[8][4];
    #pragma unroll
    for (int kk = 0; kk < 8; kk++) {
        const float* r0 = sA + (m0 + grp) * ESTR + kk * 8;
        const float* r8 = sA + (m0 + grp + 8) * ESTR + kk * 8;
        float v0 = r0[qid], v1 = r8[qid], v2 = r0[qid + 4], v3 = r8[qid + 4];
        float h0 = tf32hi(v0), h1 = tf32hi(v1), h2 = tf32hi(v2), h3 = tf32hi(v3);
        ah[kk][0] = __float_as_uint(h0); al[kk][0] = __float_as_uint(v0 - h0);
        ah[kk][1] = __float_as_uint(h1); al[kk][1] = __float_as_uint(v1 - h1);
        ah[kk][2] = __float_as_uint(h2); al[kk][2] = __float_as_uint(v2 - h2);
        ah[kk][3] = __float_as_uint(h3); al[kk][3] = __float_as_uint(v3 - h3);
    }
    const float xnA = sXn[m0 + grp];
    const float xnB = sXn[m0 + grp + 8];

    // per-token (2 rows) argmin state
    float bA = 3.4e38f, sA2 = 3.4e38f; int iA = 0;
    float bB = 3.4e38f, sB2 = 3.4e38f; int iB = 0;

    // ---- n-loop: 64 tiles of 8 codes ----
    #pragma unroll 1
    for (int n0 = 0; n0 < NK; n0 += 8) {
        float accH[4] = {0.f, 0.f, 0.f, 0.f};
        float accX[4] = {0.f, 0.f, 0.f, 0.f};
        const float* bp = sB + (n0 + grp) * ESTR;
        #pragma unroll
        for (int kk = 0; kk < 8; kk++) {
            float v0 = bp[kk * 8 + qid];
            float v1 = bp[kk * 8 + qid + 4];
            float h0 = tf32hi(v0), h1 = tf32hi(v1);
            uint32_t bh[2] = { __float_as_uint(h0), __float_as_uint(h1) };
            uint32_t bl[2] = { __float_as_uint(v0 - h0), __float_as_uint(v1 - h1) };
            mma_tf32(accH, ah[kk], bh);
            mma_tf32(accX, ah[kk], bl);
            mma_tf32(accX, al[kk], bh);
        }
        const int c0 = n0 + 2 * qid;
        const float en0 = sEn[c0], en1 = sEn[c0 + 1];
        float d0 = __fadd_rn(__fadd_rn(xnA, en0), __fmul_rn(-2.f, accH[0] + accX[0]));
        float d1 = __fadd_rn(__fadd_rn(xnA, en1), __fmul_rn(-2.f, accH[1] + accX[1]));
        float d2 = __fadd_rn(__fadd_rn(xnB, en0), __fmul_rn(-2.f, accH[2] + accX[2]));
        float d3 = __fadd_rn(__fadd_rn(xnB, en1), __fmul_rn(-2.f, accH[3] + accX[3]));
        if (d0 < bA) { sA2 = bA; bA = d0; iA = c0; } else if (d0 < sA2) sA2 = d0;
        if (d1 < bA) { sA2 = bA; bA = d1; iA = c0 + 1; } else if (d1 < sA2) sA2 = d1;
        if (d2 < bB) { sB2 = bB; bB = d2; iB = c0; } else if (d2 < sB2) sB2 = d2;
        if (d3 < bB) { sB2 = bB; bB = d3; iB = c0 + 1; } else if (d3 < sB2) sB2 = d3;
    }

    // ---- merge across the 4 lanes of each row-group (tie -> lower index) ----
    #pragma unroll
    for (int m = 1; m <= 2; m <<= 1) {
        float ob = __shfl_xor_sync(0xffffffffu, bA, m);
        float os = __shfl_xor_sync(0xffffffffu, sA2, m);
        int   oi = __shfl_xor_sync(0xffffffffu, iA, m);
        if (ob < bA || (ob == bA && oi < iA)) { sA2 = fminf(bA, os); bA = ob; iA = oi; }
        else { sA2 = fminf(sA2, ob); }
        ob = __shfl_xor_sync(0xffffffffu, bB, m);
        os = __shfl_xor_sync(0xffffffffu, sB2, m);
        oi = __shfl_xor_sync(0xffffffffu, iB, m);
        if (ob < bB || (ob == bB && oi < iB)) { sB2 = fminf(bB, os); bB = ob; iB = oi; }
        else { sB2 = fminf(sB2, ob); }
    }

    if (qid == 0) {
        int tokA = token0 + m0 + grp;
        int tokB = tokA + 8;
        out[IDX_OFF + (size_t)tokA] = (float)iA;
        out[IDX_OFF + (size_t)tokB] = (float)iB;
        if (!(sA2 - bA > THETA)) {          // tiny margin (or NaN) -> exact path
            unsigned p = atomicAdd(&g_flagn, 1u);
            if (p < FLAG_CAP) g_flags[p] = tokA;
        }
        if (!(sB2 - bB > THETA)) {
            unsigned p = atomicAdd(&g_flagn, 1u);
            if (p < FLAG_CAP) g_flags[p] = tokB;
        }
    }
}

// ================= K2: exact frozen recompute for flagged tokens =================
__global__ __launch_bounds__(512, 1) void vq_cleanup(
    const float* __restrict__ in, const float* __restrict__ emb,
    float* __restrict__ out)
{
    __shared__ float sx[ND];
    __shared__ float sxn;
    __shared__ float sen[NK];
    __shared__ unsigned long long skey;

    const int tid = threadIdx.x;
    const int wid = tid >> 5;
    const int lane = tid & 31;

    // FROZEN en (warp-tree), once per CTA
    for (int k = wid; k < NK; k += 16) {
        const float* e = emb + k * ND;
        float a = __fmul_rn(e[lane], e[lane]);
        float c = __fmul_rn(e[lane + 32], e[lane + 32]);
        float acc = __fadd_rn(a, c);
        #pragma unroll
        for (int off = 16; off; off >>= 1)
            acc = __fadd_rn(acc, __shfl_down_sync(0xffffffffu, acc, off));
        if (lane == 0) sen[k] = acc;
    }
    __syncthreads();

    unsigned count = g_flagn;
    if (count > FLAG_CAP) count = FLAG_CAP;

    for (unsigned fi = blockIdx.x; fi < count; fi += gridDim.x) {
        const int token = g_flags[fi];
        const int b = token >> 12, t = token & (NT - 1);
        if (tid < ND) sx[tid] = in[(size_t)b * ND * NT + (size_t)tid * NT + t];
        if (tid == 0) skey = 0xFFFFFFFFFFFFFFFFull;
        __syncthreads();
        if (tid == 0) {
            float xn = 0.f;
            for (int d = 0; d < ND; d++) xn = __fadd_rn(xn, __fmul_rn(sx[d], sx[d]));
            sxn = xn;
        }
        __syncthreads();
        {
            // thread k: FROZEN distance (sequential ascending fma dot)
            const float* e = emb + tid * ND;
            float a = 0.f;
            for (int d = 0; d < ND; d++) a = __fmaf_rn(sx[d], e[d], a);
            float dist = __fadd_rn(__fadd_rn(sxn, sen[tid]), __fmul_rn(-2.f, a));
            uint32_t u = __float_as_uint(dist);
            u = (u & 0x80000000u) ? ~u : (u | 0x80000000u);   // order-preserving uint
            unsigned long long key = ((unsigned long long)u << 32) | (unsigned)tid;
            atomicMin(&skey, key);          // min dist, tie -> min index (first-min)
        }
        __syncthreads();
        if (tid == 0) out[IDX_OFF + (size_t)token] = (float)(unsigned)(skey & 0xFFFFFFFFu);
        __syncthreads();
    }
}

// ================= K3: gather + loss + histogram =================
__global__ __launch_bounds__(512, 1) void vq_gather(
    const float* __restrict__ in, const float* __restrict__ emb,
    float* __restrict__ out)
{
    __shared__ unsigned int sCount[NK];
    __shared__ float sLoss;
    const int tid = threadIdx.x;
    if (tid == 0) sLoss = 0.f;
    if (tid < NK) sCount[tid] = 0u;
    __syncthreads();

    const int token = blockIdx.x * 512 + tid;
    const int b = token >> 12, t = token & (NT - 1);
    const int k = (int)out[IDX_OFF + (size_t)token];

    atomicAdd(&sCount[k], 1u);

    const float* xp = in + (size_t)b * ND * NT + t;
    const float4* eb4 = (const float4*)(emb + k * ND);
    float* qp = out + Q_OFF + (size_t)b * ND * NT + t;
    float lsum = 0.f;
    #pragma unroll
    for (int j = 0; j < ND / 4; j++) {
        float4 v = eb4[j];
        float x0 = xp[(size_t)(4 * j + 0) * NT];
        float x1 = xp[(size_t)(4 * j + 1) * NT];
        float x2 = xp[(size_t)(4 * j + 2) * NT];
        float x3 = xp[(size_t)(4 * j + 3) * NT];
        qp[(size_t)(4 * j + 0) * NT] = v.x;
        qp[(size_t)(4 * j + 1) * NT] = v.y;
        qp[(size_t)(4 * j + 2) * NT] = v.z;
        qp[(size_t)(4 * j + 3) * NT] = v.w;
        float t0 = v.x - x0, t1 = v.y - x1, t2 = v.z - x2, t3 = v.w - x3;
        lsum = __fmaf_rn(t0, t0, lsum);
        lsum = __fmaf_rn(t1, t1, lsum);
        lsum = __fmaf_rn(t2, t2, lsum);
        lsum = __fmaf_rn(t3, t3, lsum);
    }
    #pragma unroll
    for (int off = 16; off; off >>= 1)
        lsum += __shfl_down_sync(0xffffffffu, lsum, off);
    if ((tid & 31) == 0) atomicAdd(&sLoss, lsum);
    __syncthreads();
    if (tid == 0) atomicAdd(&g_loss, sLoss);
    if (tid < NK) {
        unsigned c = sCount[tid];
        if (c) atomicAdd(&g_counts[tid], c);
    }
}

// ================= K4: finalize =================
__global__ void vq_final(float* __restrict__ out) {
    __shared__ float red[32];
    int tid = threadIdx.x;
    if (tid < 32) red[tid] = 0.f;
    __syncthreads();
    unsigned c = g_counts[tid];
    float p = (float)c / (float)NTOK;
    float term = p * logf(p + 1e-10f);
    #pragma unroll
    for (int off = 16; off; off >>= 1)
        term += __shfl_down_sync(0xffffffffu, term, off);
    if ((tid & 31) == 0) red[tid >> 5] = term;
    __syncthreads();
    if (tid < 32) {
        float v = red[tid];
        #pragma unroll
        for (int off = 16; off; off >>= 1)
            v += __shfl_down_sync(0xffffffffu, v, off);
        if (tid == 0) {
            out[PERP_OFF] = expf(-v);
            out[0] = 0.25f * g_loss / (float)((size_t)NTOK * ND);
        }
    }
}

extern "C" void kernel_launch(void* const* d_in, const int* in_sizes, int n_in,
                              void* d_out, int out_size) {
    const float* in  = (const float*)d_in[0];   // [32, 64, 4096]
    const float* emb = (const float*)d_in[1];   // [512, 64]
    float* out = (float*)d_out;

    size_t smem = (size_t)(TM * ESTR + NK * ESTR + NK + TM) * sizeof(float);
    cudaFuncSetAttribute(vq_gemm, cudaFuncAttributeMaxDynamicSharedMemorySize, (int)smem);

    vq_init<<<1, 512>>>();
    vq_gemm<<<NTILE, 512, smem>>>(in, emb, out);
    vq_cleanup<<<64, 512>>>(in, emb, out);
    vq_gather<<<NTOK / 512, 512>>>(in, emb, out);
    vq_final<<<1, 512>>>(out);
}